// round 15
// baseline (speedup 1.0000x reference)
#include <cuda_runtime.h>
#include <cuda_bf16.h>

#define BATCH 2
#define CIN   256
#define CR    64
#define HH    64
#define WW    64
#define NPIX  4096
#define CAP   4096
#define SCAP  1024

#define FFMA2(d, a, b) asm("fma.rn.f32x2 %0, %1, %2, %0;" : "+l"(d) : "l"(a), "l"(b))
#define PACK2(d, lo, hi) asm("mov.b64 %0, {%1, %2};" : "=l"(d) : "f"(lo), "f"(hi))
#define CP_ASYNC16(dst, src) asm volatile("cp.async.cg.shared.global [%0], [%1], 16;" :: "r"(dst), "l"(src))
#define CP_COMMIT()  asm volatile("cp.async.commit_group;")
#define CP_WAIT0()   asm volatile("cp.async.wait_group 0;")
#define SWZ(o) ((o) ^ (((o) >> 3) & 0x70))

union F2U { unsigned long long u; float2 f; };

// device scratch
__device__ float  g_et [BATCH * NPIX * CR];          // e fp32 [n][k] (exact rescue)
__device__ __nv_bfloat16 g_etbf[BATCH * NPIX * CR];  // e bf16 [n][k] (mma operands)
__device__ float2 g_wt2[CIN * 9 * CR];               // dup-packed weights
__device__ float  g_part[8 * BATCH * CR * NPIX];     // conv partials (8 ci-slices)
__device__ float  g_xt [BATCH * NPIX * CIN];         // x transposed [b][n][c]
__device__ float  g_norm[BATCH * NPIX];              // ||e_n||^2 exact
__device__ int    g_cnt [BATCH * NPIX];              // candidate counts
__device__ int    g_cidx[(size_t)BATCH * NPIX * CAP];// candidate column lists
__device__ float  g_vals[(size_t)BATCH * NPIX * CAP];// fallback value buffer
__device__ float  g_outt[BATCH * NPIX * CIN];        // transposed accumulation [b][m][c]

// ---------------------------------------------------------------------------
__global__ __launch_bounds__(256) void zero_kernel() {
    int i = blockIdx.x * blockDim.x + threadIdx.x;
    ((float4*)g_outt)[i] = make_float4(0.f, 0.f, 0.f, 0.f);
    if (i < BATCH * NPIX) g_cnt[i] = 0;
}

__global__ __launch_bounds__(256) void wt_kernel(const float* __restrict__ w) {
    int i = blockIdx.x * blockDim.x + threadIdx.x;
    if (i < CR * CIN * 9) {
        int co = i / (CIN * 9);
        int q  = i % (CIN * 9);
        float v = w[i];
        g_wt2[q * CR + co] = make_float2(v, v);
    }
}

// ---------------------------------------------------------------------------
// g_xt[b][n][c] = x[b][c][n]
// ---------------------------------------------------------------------------
__global__ __launch_bounds__(256) void init_transpose_kernel(const float* __restrict__ x)
{
    __shared__ float s[32][33];
    const int b  = blockIdx.z;
    const int n0 = blockIdx.x * 32;
    const int c0 = blockIdx.y * 32;
    const int tx = threadIdx.x, ty = threadIdx.y;
    #pragma unroll
    for (int j = 0; j < 4; j++) {
        int c = c0 + ty + j * 8;
        s[ty + j * 8][tx] = x[(b * CIN + c) * NPIX + n0 + tx];
    }
    __syncthreads();
    #pragma unroll
    for (int j = 0; j < 4; j++) {
        int n = n0 + ty + j * 8;
        g_xt[(b * NPIX + n) * CIN + c0 + tx] = s[tx][ty + j * 8];
    }
}

// ---------------------------------------------------------------------------
// conv3x3 partial (ci-split x8), occupancy-first: ci-chunk 4 (22KB smem),
// 128 thr = 1 h-row x 64 co, thread tile 4co x 8px, launch_bounds(128,6)
// -> 6 CTAs/SM resident (24 warps, 37.5% occ). Pairs p_i=(x[2i-1],x[2i]):
// kw0 -> p0..p3, kw1 -> (p_i.hi,p_{i+1}.lo), kw2 -> p1..p4.
// ---------------------------------------------------------------------------
__global__ __launch_bounds__(128, 6) void conv_partial_kernel(const float* __restrict__ x)
{
    __shared__ __align__(16) float  s_x[4][3][72];   // x[w] at idx w+5
    __shared__ __align__(16) float2 s_w[4][9][64];   // dup-packed weights

    const int h   = blockIdx.x;
    const int cis = blockIdx.y;          // 0..7
    const int b   = blockIdx.z;
    const int cib = cis * 32;
    const int t   = threadIdx.x;
    const int cg  = t >> 3;              // 0..15 -> co = cg*4
    const int wq  = (t & 7) * 8;         // 8 consecutive px

    unsigned long long acc[4][4];
    #pragma unroll
    for (int j = 0; j < 4; j++)
        #pragma unroll
        for (int q = 0; q < 4; q++) acc[j][q] = 0ull;

    for (int ci0 = cib; ci0 < cib + 32; ci0 += 4) {
        __syncthreads();
        // x tile: 4 ci x 3 rows x 72, x[w] at idx w+5, zero halo
        for (int idx = t; idx < 4 * 3 * 72; idx += 128) {
            int ci  = idx / 216;
            int rem = idx % 216;
            int r   = rem / 72;
            int cw  = rem % 72;
            int hh  = h - 1 + r;
            int ww  = cw - 5;
            float v = 0.f;
            if (hh >= 0 && hh < HH && ww >= 0 && ww < WW)
                v = x[((b * CIN + ci0 + ci) * HH + hh) * WW + ww];
            s_x[ci][r][cw] = v;
        }
        // weights: 4 ci x 9 kk x 64 co
        for (int idx = t; idx < 4 * 9 * 64; idx += 128) {
            int ci  = idx / 576;
            int rem = idx % 576;
            int kk  = rem >> 6;
            int co  = rem & 63;
            s_w[ci][kk][co] = g_wt2[((ci0 + ci) * 9 + kk) * CR + co];
        }
        __syncthreads();

        #pragma unroll
        for (int ci = 0; ci < 4; ci++) {
            #pragma unroll
            for (int kh = 0; kh < 3; kh++) {
                const float* xr = &s_x[ci][kh][0];
                // p0..p4 : aligned pair loads (x[wq-1] at idx wq+4)
                ulonglong2 P01 = *(const ulonglong2*)&xr[wq + 4];
                ulonglong2 P23 = *(const ulonglong2*)&xr[wq + 8];
                unsigned long long P4 = *(const unsigned long long*)&xr[wq + 12];

                unsigned long long p[5] = {P01.x, P01.y, P23.x, P23.y, P4};
                unsigned long long q[4];
                #pragma unroll
                for (int i = 0; i < 4; i++) {
                    F2U lo, hi;
                    lo.u = p[i]; hi.u = p[i + 1];
                    PACK2(q[i], lo.f.y, hi.f.x);
                }

                // kw = 0
                {
                    ulonglong2 w01 = *(const ulonglong2*)&s_w[ci][kh * 3 + 0][cg * 4];
                    ulonglong2 w23 = *(const ulonglong2*)&s_w[ci][kh * 3 + 0][cg * 4 + 2];
                    #pragma unroll
                    for (int i = 0; i < 4; i++) {
                        FFMA2(acc[0][i], w01.x, p[i]);
                        FFMA2(acc[1][i], w01.y, p[i]);
                        FFMA2(acc[2][i], w23.x, p[i]);
                        FFMA2(acc[3][i], w23.y, p[i]);
                    }
                }
                // kw = 1
                {
                    ulonglong2 w01 = *(const ulonglong2*)&s_w[ci][kh * 3 + 1][cg * 4];
                    ulonglong2 w23 = *(const ulonglong2*)&s_w[ci][kh * 3 + 1][cg * 4 + 2];
                    #pragma unroll
                    for (int i = 0; i < 4; i++) {
                        FFMA2(acc[0][i], w01.x, q[i]);
                        FFMA2(acc[1][i], w01.y, q[i]);
                        FFMA2(acc[2][i], w23.x, q[i]);
                        FFMA2(acc[3][i], w23.y, q[i]);
                    }
                }
                // kw = 2
                {
                    ulonglong2 w01 = *(const ulonglong2*)&s_w[ci][kh * 3 + 2][cg * 4];
                    ulonglong2 w23 = *(const ulonglong2*)&s_w[ci][kh * 3 + 2][cg * 4 + 2];
                    #pragma unroll
                    for (int i = 0; i < 4; i++) {
                        FFMA2(acc[0][i], w01.x, p[i + 1]);
                        FFMA2(acc[1][i], w01.y, p[i + 1]);
                        FFMA2(acc[2][i], w23.x, p[i + 1]);
                        FFMA2(acc[3][i], w23.y, p[i + 1]);
                    }
                }
            }
        }
    }

    float* dst = g_part + ((size_t)(cis * BATCH + b) * CR) * NPIX;
    const int pix = h * WW + wq;
    #pragma unroll
    for (int j = 0; j < 4; j++) {
        const int co = cg * 4 + j;
        F2U u0, u1, u2, u3;
        u0.u = acc[j][0]; u1.u = acc[j][1]; u2.u = acc[j][2]; u3.u = acc[j][3];
        *(float4*)&dst[co * NPIX + pix]     = make_float4(u0.f.x, u0.f.y, u1.f.x, u1.f.y);
        *(float4*)&dst[co * NPIX + pix + 4] = make_float4(u2.f.x, u2.f.y, u3.f.x, u3.f.y);
    }
}

// ---------------------------------------------------------------------------
// epilogue: sum 8 partial slabs + bias + BN + PReLU -> g_et, g_etbf, g_norm
// ---------------------------------------------------------------------------
__global__ __launch_bounds__(256) void conv_epilogue_kernel(
    const float* __restrict__ cb, const float* __restrict__ gamma,
    const float* __restrict__ beta, const float* __restrict__ mean,
    const float* __restrict__ var, const float* __restrict__ prelu)
{
    __shared__ float s_v[64][33];
    __shared__ float s_nrm[8][32];

    const int b    = blockIdx.y;
    const int n0   = blockIdx.x * 32;
    const int t    = threadIdx.x;
    const int w    = t >> 5;
    const int lane = t & 31;
    const float slope = prelu[0];

    float nacc = 0.f;
    #pragma unroll
    for (int j = 0; j < 8; j++) {
        const int co = w * 8 + j;
        const size_t off = (size_t)co * NPIX + n0 + lane;
        float v = 0.f;
        #pragma unroll
        for (int s = 0; s < 8; s++)
            v += g_part[((size_t)(s * BATCH + b) * CR) * NPIX + off];
        const float sc   = gamma[co] * rsqrtf(var[co] + 1e-5f);
        const float base = (cb[co] - mean[co]) * sc + beta[co];
        float y = v * sc + base;
        y = (y >= 0.f) ? y : slope * y;
        s_v[co][lane] = y;
        nacc += y * y;
    }
    s_nrm[w][lane] = nacc;
    __syncthreads();

    if (w == 0) {
        float s = 0.f;
        #pragma unroll
        for (int k = 0; k < 8; k++) s += s_nrm[k][lane];
        g_norm[b * NPIX + n0 + lane] = s;
    }

    const int n  = t >> 3;
    const int c8 = (t & 7) * 8;
    float vals[8];
    #pragma unroll
    for (int j = 0; j < 8; j++) vals[j] = s_v[c8 + j][n];

    float* et = g_et + ((size_t)(b * NPIX) + n0 + n) * CR + c8;
    *(float4*)et       = make_float4(vals[0], vals[1], vals[2], vals[3]);
    *(float4*)(et + 4) = make_float4(vals[4], vals[5], vals[6], vals[7]);

    unsigned q0, q1, q2, q3;
    asm("cvt.rn.bf16x2.f32 %0, %1, %2;" : "=r"(q0) : "f"(vals[1]), "f"(vals[0]));
    asm("cvt.rn.bf16x2.f32 %0, %1, %2;" : "=r"(q1) : "f"(vals[3]), "f"(vals[2]));
    asm("cvt.rn.bf16x2.f32 %0, %1, %2;" : "=r"(q2) : "f"(vals[5]), "f"(vals[4]));
    asm("cvt.rn.bf16x2.f32 %0, %1, %2;" : "=r"(q3) : "f"(vals[7]), "f"(vals[6]));
    *(uint4*)(g_etbf + ((size_t)(b * NPIX) + n0 + n) * CR + c8) = make_uint4(q0, q1, q2, q3);
}

// ---------------------------------------------------------------------------
// Symmetric tensor-core GEMM + filter (i<=j tiles, dual-append off-diagonal)
// ---------------------------------------------------------------------------
#define MMA(d, a0, a1, a2, a3, b0, b1)                                        \
    asm volatile("mma.sync.aligned.m16n8k16.row.col.f32.bf16.bf16.f32 "       \
                 "{%0,%1,%2,%3}, {%4,%5,%6,%7}, {%8,%9}, {%0,%1,%2,%3};"      \
                 : "+f"(d[0]), "+f"(d[1]), "+f"(d[2]), "+f"(d[3])             \
                 : "r"(a0), "r"(a1), "r"(a2), "r"(a3), "r"(b0), "r"(b1))

#define LDSM4(r0, r1, r2, r3, addr)                                           \
    asm volatile("ldmatrix.sync.aligned.m8n8.x4.shared.b16 {%0,%1,%2,%3}, [%4];" \
                 : "=r"(r0), "=r"(r1), "=r"(r2), "=r"(r3) : "r"(addr))

__global__ __launch_bounds__(256) void gemm_filter_sym_kernel()
{
    __shared__ __align__(1024) char s_A[128 * 128];
    __shared__ __align__(1024) char s_B[128 * 128];
    __shared__ float s_nC[128];

    const int bi = blockIdx.y;
    const int bj = blockIdx.x;
    if (bi > bj) return;
    const bool offdiag = (bi != bj);

    const int b  = blockIdx.z;
    const int n0 = bi * 128;
    const int m0 = bj * 128;
    const int t  = threadIdx.x;
    const int wid  = t >> 5;
    const int lane = t & 31;
    const int wr = wid >> 1;
    const int wc = wid & 1;
    const int bN = b * NPIX;

    {
        unsigned sa = (unsigned)__cvta_generic_to_shared(s_A);
        unsigned sb = (unsigned)__cvta_generic_to_shared(s_B);
        const char* Ab = (const char*)g_etbf + (size_t)(bN + n0) * 128;
        const char* Bb = (const char*)g_etbf + (size_t)(bN + m0) * 128;
        #pragma unroll
        for (int j = 0; j < 4; j++) {
            int idx = t + j * 256;
            unsigned off = (unsigned)((idx >> 3) * 128 + (idx & 7) * 16);
            CP_ASYNC16(sa + SWZ(off), Ab + off);
            CP_ASYNC16(sb + SWZ(off), Bb + off);
        }
        if (t < 128) s_nC[t] = g_norm[bN + m0 + t];
        CP_COMMIT();
        CP_WAIT0();
    }
    __syncthreads();

    float acc[2][8][4];
    #pragma unroll
    for (int mg = 0; mg < 2; mg++)
        #pragma unroll
        for (int ng = 0; ng < 8; ng++)
            #pragma unroll
            for (int q = 0; q < 4; q++) acc[mg][ng][q] = 0.f;

    const unsigned saB = (unsigned)__cvta_generic_to_shared(s_A);
    const unsigned sbB = (unsigned)__cvta_generic_to_shared(s_B);
    const unsigned hb  = (unsigned)((lane >> 4) * 16);
    const unsigned rA0 = (unsigned)((wr * 32 + (lane & 15)) * 128);
    const unsigned rA1 = rA0 + 16 * 128;
    const unsigned rB0 = (unsigned)((wc * 64 + (lane & 15)) * 128);

    #pragma unroll
    for (int kc = 0; kc < 4; kc++) {
        unsigned a0[4], a1[4];
        LDSM4(a0[0], a0[1], a0[2], a0[3], saB + SWZ(rA0 + kc * 32 + hb));
        LDSM4(a1[0], a1[1], a1[2], a1[3], saB + SWZ(rA1 + kc * 32 + hb));
        #pragma unroll
        for (int ng16 = 0; ng16 < 4; ng16++) {
            unsigned b0, b1, b2, b3;
            LDSM4(b0, b1, b2, b3,
                  sbB + SWZ(rB0 + (unsigned)(ng16 * 16 * 128) + kc * 32 + hb));
            MMA(acc[0][2 * ng16],     a0[0], a0[1], a0[2], a0[3], b0, b2);
            MMA(acc[0][2 * ng16 + 1], a0[0], a0[1], a0[2], a0[3], b1, b3);
            MMA(acc[1][2 * ng16],     a1[0], a1[1], a1[2], a1[3], b0, b2);
            MMA(acc[1][2 * ng16 + 1], a1[0], a1[1], a1[2], a1[3], b1, b3);
        }
    }

    #pragma unroll
    for (int mg = 0; mg < 2; mg++) {
        const int r0l = wr * 32 + mg * 16 + (lane >> 2);
        const int r1l = r0l + 8;
        const int r0g = bN + n0 + r0l;
        const int r1g = r0g + 8;
        const float thr0 = g_norm[r0g] - 2.0f;
        const float thr1 = g_norm[r1g] - 2.0f;
        int* cl0 = g_cidx + ((size_t)r0g << 12);
        int* cl1 = g_cidx + ((size_t)r1g << 12);
        #pragma unroll
        for (int ng = 0; ng < 8; ng++) {
            const int coll = wc * 64 + ng * 8 + 2 * (lane & 3);
            const int colg = m0 + coll;
            const float* a = acc[mg][ng];
            if (a[0] > thr0) { int p = atomicAdd(&g_cnt[r0g], 1); cl0[p] = colg; }
            if (a[1] > thr0) { int p = atomicAdd(&g_cnt[r0g], 1); cl0[p] = colg + 1; }
            if (a[2] > thr1) { int p = atomicAdd(&g_cnt[r1g], 1); cl1[p] = colg; }
            if (a[3] > thr1) { int p = atomicAdd(&g_cnt[r1g], 1); cl1[p] = colg + 1; }
            if (offdiag) {
                const float tc0 = s_nC[coll] - 2.0f;
                const float tc1 = s_nC[coll + 1] - 2.0f;
                const int c0g = bN + colg;
                const int c1g = c0g + 1;
                if (a[0] > tc0) { int p = atomicAdd(&g_cnt[c0g], 1);
                                  g_cidx[((size_t)c0g << 12) + p] = n0 + r0l; }
                if (a[1] > tc1) { int p = atomicAdd(&g_cnt[c1g], 1);
                                  g_cidx[((size_t)c1g << 12) + p] = n0 + r0l; }
                if (a[2] > tc0) { int p = atomicAdd(&g_cnt[c0g], 1);
                                  g_cidx[((size_t)c0g << 12) + p] = n0 + r1l; }
                if (a[3] > tc1) { int p = atomicAdd(&g_cnt[c1g], 1);
                                  g_cidx[((size_t)c1g << 12) + p] = n0 + r1l; }
            }
        }
    }
}

// ---------------------------------------------------------------------------
// Solve (block per row): exact fp32 dots, Michelot (tau0=-1), coalesced scatter
// ---------------------------------------------------------------------------
__global__ __launch_bounds__(256) void solve_scatter_kernel()
{
    __shared__ int   s_idx[SCAP];
    __shared__ float s_val[SCAP];
    __shared__ float s_rf[8];
    __shared__ int   s_ri[8];
    __shared__ float s_Mex;
    __shared__ int   s_pk;
    __shared__ int   s_pidx[SCAP];
    __shared__ float s_pv[SCAP];

    const int n    = blockIdx.x;
    const int b    = blockIdx.y;
    const int t    = threadIdx.x;
    const int wid  = t >> 5;
    const int lane = t & 31;
    const int bN   = b * NPIX;
    const int row  = bN + n;

    const int c = g_cnt[row];
    if (t == 0) s_pk = 0;
    int*   gl = g_cidx + ((size_t)row << 12);
    const bool small = (c <= SCAP);
    int*   idx = small ? s_idx : gl;
    float* val = small ? s_val : (g_vals + ((size_t)row << 12));
    if (small)
        for (int j = t; j < c; j += 256) s_idx[j] = gl[j];
    __syncthreads();

    {
        const float2 en = *(const float2*)&g_et[(size_t)row * CR + lane * 2];
        for (int j = wid; j < c; j += 8) {
            int mcol = idx[j];
            float2 em = *(const float2*)&g_et[(size_t)(bN + mcol) * CR + lane * 2];
            float sum = en.x * em.x + en.y * em.y;
            #pragma unroll
            for (int o = 16; o; o >>= 1) sum += __shfl_xor_sync(0xffffffffu, sum, o);
            if (lane == 0) val[j] = sum;
        }
    }
    __syncthreads();

    {
        float mm = -3.0e38f;
        for (int j = t; j < c; j += 256) mm = fmaxf(mm, val[j]);
        #pragma unroll
        for (int o = 16; o; o >>= 1) mm = fmaxf(mm, __shfl_xor_sync(0xffffffffu, mm, o));
        if (lane == 0) s_rf[wid] = mm;
        __syncthreads();
        if (t == 0) {
            float v = s_rf[0];
            #pragma unroll
            for (int w = 1; w < 8; w++) v = fmaxf(v, s_rf[w]);
            s_Mex = v;
        }
        __syncthreads();
    }
    const float Mex = s_Mex;

    float tau = -1.0f;
    int prev = -1;
    for (int it = 0; it < 32; it++) {
        float ss = 0.f; int cnt = 0;
        for (int j = t; j < c; j += 256) {
            float z = val[j] - Mex;
            if (z > tau) { ss += z; cnt++; }
        }
        #pragma unroll
        for (int o = 16; o; o >>= 1) {
            ss  += __shfl_xor_sync(0xffffffffu, ss, o);
            cnt += __shfl_xor_sync(0xffffffffu, cnt, o);
        }
        if (lane == 0) { s_rf[wid] = ss; s_ri[wid] = cnt; }
        __syncthreads();
        float tss = 0.f; int tcn = 0;
        #pragma unroll
        for (int w = 0; w < 8; w++) { tss += s_rf[w]; tcn += s_ri[w]; }
        __syncthreads();
        tau = (tss - 1.f) / (float)tcn;
        if (tcn == prev) break;
        prev = tcn;
    }

    const unsigned lt_mask = (1u << lane) - 1u;
    for (int j0 = 0; j0 < c; j0 += 256) {
        int j = j0 + t;
        float p = 0.f;
        bool pos = false;
        if (j < c) {
            p = val[j] - Mex - tau;
            pos = p > 0.f;
        }
        unsigned mk = __ballot_sync(0xffffffffu, pos);
        int base = 0;
        if (lane == 0 && mk) base = atomicAdd(&s_pk, __popc(mk));
        base = __shfl_sync(0xffffffffu, base, 0);
        if (pos) {
            int pi = base + __popc(mk & lt_mask);
            if (pi < SCAP) { s_pidx[pi] = idx[j]; s_pv[pi] = p; }
        }
    }
    __syncthreads();

    const float xv = g_xt[(size_t)row * CIN + t];
    float* ot = g_outt + (size_t)bN * CIN;
    if (s_pk <= SCAP) {
        const int kp = s_pk;
        for (int jj = 0; jj < kp; jj++)
            atomicAdd(&ot[(size_t)s_pidx[jj] * CIN + t], s_pv[jj] * xv);
    } else {
        for (int j = 0; j < c; j++) {
            float p = val[j] - Mex - tau;
            if (p > 0.f)
                atomicAdd(&ot[(size_t)idx[j] * CIN + t], p * xv);
        }
    }
}

// ---------------------------------------------------------------------------
// out[b][c][n] = x[b][c][n] + outt[b][n][c]
// ---------------------------------------------------------------------------
__global__ __launch_bounds__(256) void final_add_kernel(
    const float* __restrict__ x, float* __restrict__ out)
{
    __shared__ float s[32][33];
    const int b  = blockIdx.z;
    const int n0 = blockIdx.x * 32;
    const int c0 = blockIdx.y * 32;
    const int tx = threadIdx.x, ty = threadIdx.y;
    #pragma unroll
    for (int j = 0; j < 4; j++) {
        int n = n0 + ty + j * 8;
        s[ty + j * 8][tx] = g_outt[((size_t)(b * NPIX) + n) * CIN + c0 + tx];
    }
    __syncthreads();
    #pragma unroll
    for (int j = 0; j < 4; j++) {
        int c = c0 + ty + j * 8;
        size_t o = (size_t)(b * CIN + c) * NPIX + n0 + tx;
        out[o] = x[o] + s[tx][ty + j * 8];
    }
}

// ---------------------------------------------------------------------------
extern "C" void kernel_launch(void* const* d_in, const int* in_sizes, int n_in,
                              void* d_out, int out_size)
{
    const float* x      = (const float*)d_in[0];
    const float* conv_w = (const float*)d_in[1];
    const float* conv_b = (const float*)d_in[2];
    const float* gamma  = (const float*)d_in[3];
    const float* beta   = (const float*)d_in[4];
    const float* mean   = (const float*)d_in[5];
    const float* var    = (const float*)d_in[6];
    const float* prelu  = (const float*)d_in[7];
    float* out = (float*)d_out;

    // conv in the profiled (4th) slot
    zero_kernel<<<2048, 256>>>();

    wt_kernel<<<(CR * CIN * 9 + 255) / 256, 256>>>(conv_w);

    init_transpose_kernel<<<dim3(NPIX / 32, CIN / 32, BATCH), dim3(32, 8)>>>(x);

    conv_partial_kernel<<<dim3(HH, 8, BATCH), 128>>>(x);

    conv_epilogue_kernel<<<dim3(NPIX / 32, BATCH), 256>>>(
        conv_b, gamma, beta, mean, var, prelu);

    gemm_filter_sym_kernel<<<dim3(32, 32, BATCH), 256>>>();

    solve_scatter_kernel<<<dim3(NPIX, BATCH), 256>>>();

    final_add_kernel<<<dim3(NPIX / 32, CIN / 32, BATCH), dim3(32, 8)>>>(x, out);
}

// round 16
// speedup vs baseline: 1.1633x; 1.1633x over previous
#include <cuda_runtime.h>
#include <cuda_bf16.h>

#define BATCH 2
#define CIN   256
#define CR    64
#define HH    64
#define WW    64
#define NPIX  4096
#define CAP   4096
#define SCAP  1024

#define FFMA2(d, a, b) asm("fma.rn.f32x2 %0, %1, %2, %0;" : "+l"(d) : "l"(a), "l"(b))
#define PACK2(d, lo, hi) asm("mov.b64 %0, {%1, %2};" : "=l"(d) : "f"(lo), "f"(hi))
#define CP_ASYNC16(dst, src) asm volatile("cp.async.cg.shared.global [%0], [%1], 16;" :: "r"(dst), "l"(src))
#define CP_COMMIT()  asm volatile("cp.async.commit_group;")
#define CP_WAIT0()   asm volatile("cp.async.wait_group 0;")
#define SWZ(o) ((o) ^ (((o) >> 3) & 0x70))

union F2U { unsigned long long u; float2 f; };

// device scratch
__device__ float  g_et [BATCH * NPIX * CR];          // e fp32 [n][k] (exact rescue)
__device__ __nv_bfloat16 g_etbf[BATCH * NPIX * CR];  // e bf16 [n][k] (mma operands)
__device__ float2 g_wt2[CIN * 9 * CR];               // dup-packed weights
__device__ float  g_part[4 * BATCH * CR * NPIX];     // conv partials (4 ci-slices)
__device__ float  g_xt [BATCH * NPIX * CIN];         // x transposed [b][n][c]
__device__ float  g_norm[BATCH * NPIX];              // ||e_n||^2 exact
__device__ int    g_cnt [BATCH * NPIX];              // candidate counts
__device__ int    g_cidx[(size_t)BATCH * NPIX * CAP];// candidate column lists
__device__ float  g_vals[(size_t)BATCH * NPIX * CAP];// fallback value buffer
__device__ float  g_outt[BATCH * NPIX * CIN];        // transposed accumulation [b][m][c]

// ---------------------------------------------------------------------------
__global__ __launch_bounds__(256) void zero_kernel() {
    int i = blockIdx.x * blockDim.x + threadIdx.x;
    ((float4*)g_outt)[i] = make_float4(0.f, 0.f, 0.f, 0.f);
    if (i < BATCH * NPIX) g_cnt[i] = 0;
}

__global__ __launch_bounds__(256) void wt_kernel(const float* __restrict__ w) {
    int i = blockIdx.x * blockDim.x + threadIdx.x;
    if (i < CR * CIN * 9) {
        int co = i / (CIN * 9);
        int q  = i % (CIN * 9);
        float v = w[i];
        g_wt2[q * CR + co] = make_float2(v, v);
    }
}

// ---------------------------------------------------------------------------
// g_xt[b][n][c] = x[b][c][n]
// ---------------------------------------------------------------------------
__global__ __launch_bounds__(256) void init_transpose_kernel(const float* __restrict__ x)
{
    __shared__ float s[32][33];
    const int b  = blockIdx.z;
    const int n0 = blockIdx.x * 32;
    const int c0 = blockIdx.y * 32;
    const int tx = threadIdx.x, ty = threadIdx.y;
    #pragma unroll
    for (int j = 0; j < 4; j++) {
        int c = c0 + ty + j * 8;
        s[ty + j * 8][tx] = x[(b * CIN + c) * NPIX + n0 + tx];
    }
    __syncthreads();
    #pragma unroll
    for (int j = 0; j < 4; j++) {
        int n = n0 + ty + j * 8;
        g_xt[(b * NPIX + n) * CIN + c0 + tx] = s[tx][ty + j * 8];
    }
}

// ---------------------------------------------------------------------------
// conv3x3 partial (ci-split x4, chunk 8). 256 thr = 2 h-rows x 64 co,
// thread 4co x 8px. Fill surgery: weight fill = pure linear uint4 memcpy
// (smem layout mirrors g_wt2 chunk); x-fill indices hoisted out of the chunk
// loop (only predicated LDG+STS per chunk). Pairs p_i=(x[2i-1],x[2i]):
// kw0 -> p0..p3, kw1 -> q_i=(p_i.hi,p_{i+1}.lo), kw2 -> p1..p4.
// ---------------------------------------------------------------------------
__global__ __launch_bounds__(256) void conv_partial_kernel(const float* __restrict__ x)
{
    __shared__ __align__(16) float  s_x[8 * 4 * 72];   // [ci][r][72], x[w] at col w+5
    __shared__ __align__(16) float2 s_w[8 * 9 * 64];   // linear mirror of g_wt2 chunk

    const int h0  = blockIdx.x * 2;
    const int cis = blockIdx.y;          // 0..3
    const int b   = blockIdx.z;
    const int cib = cis * 64;
    const int t   = threadIdx.x;
    const int cg  = t >> 4;              // 0..15 -> co = cg*4
    const int pg  = t & 15;
    const int row = pg >> 3;             // 0..1
    const int wq  = (pg & 7) * 8;        // 8 consecutive px

    // hoisted x-fill indices (chunk-invariant)
    int  xoff[9];
    bool xval[9];
    #pragma unroll
    for (int j = 0; j < 9; j++) {
        int idx = t + j * 256;           // 0..2303
        int ci  = idx / 288;
        int rem = idx % 288;
        int r   = rem / 72;
        int cw  = rem % 72;
        int hh  = h0 - 1 + r;
        int ww  = cw - 5;
        xval[j] = (hh >= 0 && hh < HH && ww >= 0 && ww < WW);
        xoff[j] = ((b * CIN + ci) * HH + hh) * WW + ww;
    }

    unsigned long long acc[4][4];
    #pragma unroll
    for (int j = 0; j < 4; j++)
        #pragma unroll
        for (int q = 0; q < 4; q++) acc[j][q] = 0ull;

    for (int ci0 = cib; ci0 < cib + 64; ci0 += 8) {
        __syncthreads();
        // x fill: predicated LDG + STS only
        const float* xc = x + ci0 * (HH * WW);
        #pragma unroll
        for (int j = 0; j < 9; j++) {
            float v = 0.f;
            if (xval[j]) v = xc[xoff[j]];
            s_x[t + j * 256] = v;
        }
        // weight fill: pure linear memcpy (2304 uint4)
        {
            const uint4* wsrc = (const uint4*)(g_wt2 + ci0 * 9 * CR);
            uint4* wdst = (uint4*)s_w;
            #pragma unroll
            for (int j = 0; j < 9; j++)
                wdst[t + j * 256] = wsrc[t + j * 256];
        }
        __syncthreads();

        #pragma unroll
        for (int ci = 0; ci < 8; ci++) {
            #pragma unroll
            for (int kh = 0; kh < 3; kh++) {
                const float* xr = &s_x[ci * 288 + (row + kh) * 72];
                ulonglong2 P01 = *(const ulonglong2*)&xr[wq + 4];
                ulonglong2 P23 = *(const ulonglong2*)&xr[wq + 8];
                unsigned long long P4 = *(const unsigned long long*)&xr[wq + 12];

                unsigned long long p[5] = {P01.x, P01.y, P23.x, P23.y, P4};
                unsigned long long q[4];
                #pragma unroll
                for (int i = 0; i < 4; i++) {
                    F2U lo, hi;
                    lo.u = p[i]; hi.u = p[i + 1];
                    PACK2(q[i], lo.f.y, hi.f.x);
                }

                const float2* wb = &s_w[(ci * 9 + kh * 3) * 64 + cg * 4];
                // kw = 0
                {
                    ulonglong2 w01 = *(const ulonglong2*)(wb);
                    ulonglong2 w23 = *(const ulonglong2*)(wb + 2);
                    #pragma unroll
                    for (int i = 0; i < 4; i++) {
                        FFMA2(acc[0][i], w01.x, p[i]);
                        FFMA2(acc[1][i], w01.y, p[i]);
                        FFMA2(acc[2][i], w23.x, p[i]);
                        FFMA2(acc[3][i], w23.y, p[i]);
                    }
                }
                // kw = 1
                {
                    ulonglong2 w01 = *(const ulonglong2*)(wb + 64);
                    ulonglong2 w23 = *(const ulonglong2*)(wb + 66);
                    #pragma unroll
                    for (int i = 0; i < 4; i++) {
                        FFMA2(acc[0][i], w01.x, q[i]);
                        FFMA2(acc[1][i], w01.y, q[i]);
                        FFMA2(acc[2][i], w23.x, q[i]);
                        FFMA2(acc[3][i], w23.y, q[i]);
                    }
                }
                // kw = 2
                {
                    ulonglong2 w01 = *(const ulonglong2*)(wb + 128);
                    ulonglong2 w23 = *(const ulonglong2*)(wb + 130);
                    #pragma unroll
                    for (int i = 0; i < 4; i++) {
                        FFMA2(acc[0][i], w01.x, p[i + 1]);
                        FFMA2(acc[1][i], w01.y, p[i + 1]);
                        FFMA2(acc[2][i], w23.x, p[i + 1]);
                        FFMA2(acc[3][i], w23.y, p[i + 1]);
                    }
                }
            }
        }
    }

    float* dst = g_part + ((size_t)(cis * BATCH + b) * CR) * NPIX;
    const int pix = (h0 + row) * WW + wq;
    #pragma unroll
    for (int j = 0; j < 4; j++) {
        const int co = cg * 4 + j;
        F2U u0, u1, u2, u3;
        u0.u = acc[j][0]; u1.u = acc[j][1]; u2.u = acc[j][2]; u3.u = acc[j][3];
        *(float4*)&dst[co * NPIX + pix]     = make_float4(u0.f.x, u0.f.y, u1.f.x, u1.f.y);
        *(float4*)&dst[co * NPIX + pix + 4] = make_float4(u2.f.x, u2.f.y, u3.f.x, u3.f.y);
    }
}

// ---------------------------------------------------------------------------
// epilogue: sum 4 partial slabs + bias + BN + PReLU -> g_et, g_etbf, g_norm
// ---------------------------------------------------------------------------
__global__ __launch_bounds__(256) void conv_epilogue_kernel(
    const float* __restrict__ cb, const float* __restrict__ gamma,
    const float* __restrict__ beta, const float* __restrict__ mean,
    const float* __restrict__ var, const float* __restrict__ prelu)
{
    __shared__ float s_v[64][33];
    __shared__ float s_nrm[8][32];

    const int b    = blockIdx.y;
    const int n0   = blockIdx.x * 32;
    const int t    = threadIdx.x;
    const int w    = t >> 5;
    const int lane = t & 31;
    const float slope = prelu[0];

    float nacc = 0.f;
    #pragma unroll
    for (int j = 0; j < 8; j++) {
        const int co = w * 8 + j;
        const size_t off = (size_t)co * NPIX + n0 + lane;
        float v = g_part[((size_t)(0 * BATCH + b) * CR) * NPIX + off]
                + g_part[((size_t)(1 * BATCH + b) * CR) * NPIX + off]
                + g_part[((size_t)(2 * BATCH + b) * CR) * NPIX + off]
                + g_part[((size_t)(3 * BATCH + b) * CR) * NPIX + off];
        const float sc   = gamma[co] * rsqrtf(var[co] + 1e-5f);
        const float base = (cb[co] - mean[co]) * sc + beta[co];
        float y = v * sc + base;
        y = (y >= 0.f) ? y : slope * y;
        s_v[co][lane] = y;
        nacc += y * y;
    }
    s_nrm[w][lane] = nacc;
    __syncthreads();

    if (w == 0) {
        float s = 0.f;
        #pragma unroll
        for (int k = 0; k < 8; k++) s += s_nrm[k][lane];
        g_norm[b * NPIX + n0 + lane] = s;
    }

    const int n  = t >> 3;
    const int c8 = (t & 7) * 8;
    float vals[8];
    #pragma unroll
    for (int j = 0; j < 8; j++) vals[j] = s_v[c8 + j][n];

    float* et = g_et + ((size_t)(b * NPIX) + n0 + n) * CR + c8;
    *(float4*)et       = make_float4(vals[0], vals[1], vals[2], vals[3]);
    *(float4*)(et + 4) = make_float4(vals[4], vals[5], vals[6], vals[7]);

    unsigned q0, q1, q2, q3;
    asm("cvt.rn.bf16x2.f32 %0, %1, %2;" : "=r"(q0) : "f"(vals[1]), "f"(vals[0]));
    asm("cvt.rn.bf16x2.f32 %0, %1, %2;" : "=r"(q1) : "f"(vals[3]), "f"(vals[2]));
    asm("cvt.rn.bf16x2.f32 %0, %1, %2;" : "=r"(q2) : "f"(vals[5]), "f"(vals[4]));
    asm("cvt.rn.bf16x2.f32 %0, %1, %2;" : "=r"(q3) : "f"(vals[7]), "f"(vals[6]));
    *(uint4*)(g_etbf + ((size_t)(b * NPIX) + n0 + n) * CR + c8) = make_uint4(q0, q1, q2, q3);
}

// ---------------------------------------------------------------------------
// Symmetric tensor-core GEMM + filter (i<=j tiles, dual-append off-diagonal)
// ---------------------------------------------------------------------------
#define MMA(d, a0, a1, a2, a3, b0, b1)                                        \
    asm volatile("mma.sync.aligned.m16n8k16.row.col.f32.bf16.bf16.f32 "       \
                 "{%0,%1,%2,%3}, {%4,%5,%6,%7}, {%8,%9}, {%0,%1,%2,%3};"      \
                 : "+f"(d[0]), "+f"(d[1]), "+f"(d[2]), "+f"(d[3])             \
                 : "r"(a0), "r"(a1), "r"(a2), "r"(a3), "r"(b0), "r"(b1))

#define LDSM4(r0, r1, r2, r3, addr)                                           \
    asm volatile("ldmatrix.sync.aligned.m8n8.x4.shared.b16 {%0,%1,%2,%3}, [%4];" \
                 : "=r"(r0), "=r"(r1), "=r"(r2), "=r"(r3) : "r"(addr))

__global__ __launch_bounds__(256) void gemm_filter_sym_kernel()
{
    __shared__ __align__(1024) char s_A[128 * 128];
    __shared__ __align__(1024) char s_B[128 * 128];
    __shared__ float s_nC[128];

    const int bi = blockIdx.y;
    const int bj = blockIdx.x;
    if (bi > bj) return;
    const bool offdiag = (bi != bj);

    const int b  = blockIdx.z;
    const int n0 = bi * 128;
    const int m0 = bj * 128;
    const int t  = threadIdx.x;
    const int wid  = t >> 5;
    const int lane = t & 31;
    const int wr = wid >> 1;
    const int wc = wid & 1;
    const int bN = b * NPIX;

    {
        unsigned sa = (unsigned)__cvta_generic_to_shared(s_A);
        unsigned sb = (unsigned)__cvta_generic_to_shared(s_B);
        const char* Ab = (const char*)g_etbf + (size_t)(bN + n0) * 128;
        const char* Bb = (const char*)g_etbf + (size_t)(bN + m0) * 128;
        #pragma unroll
        for (int j = 0; j < 4; j++) {
            int idx = t + j * 256;
            unsigned off = (unsigned)((idx >> 3) * 128 + (idx & 7) * 16);
            CP_ASYNC16(sa + SWZ(off), Ab + off);
            CP_ASYNC16(sb + SWZ(off), Bb + off);
        }
        if (t < 128) s_nC[t] = g_norm[bN + m0 + t];
        CP_COMMIT();
        CP_WAIT0();
    }
    __syncthreads();

    float acc[2][8][4];
    #pragma unroll
    for (int mg = 0; mg < 2; mg++)
        #pragma unroll
        for (int ng = 0; ng < 8; ng++)
            #pragma unroll
            for (int q = 0; q < 4; q++) acc[mg][ng][q] = 0.f;

    const unsigned saB = (unsigned)__cvta_generic_to_shared(s_A);
    const unsigned sbB = (unsigned)__cvta_generic_to_shared(s_B);
    const unsigned hb  = (unsigned)((lane >> 4) * 16);
    const unsigned rA0 = (unsigned)((wr * 32 + (lane & 15)) * 128);
    const unsigned rA1 = rA0 + 16 * 128;
    const unsigned rB0 = (unsigned)((wc * 64 + (lane & 15)) * 128);

    #pragma unroll
    for (int kc = 0; kc < 4; kc++) {
        unsigned a0[4], a1[4];
        LDSM4(a0[0], a0[1], a0[2], a0[3], saB + SWZ(rA0 + kc * 32 + hb));
        LDSM4(a1[0], a1[1], a1[2], a1[3], saB + SWZ(rA1 + kc * 32 + hb));
        #pragma unroll
        for (int ng16 = 0; ng16 < 4; ng16++) {
            unsigned b0, b1, b2, b3;
            LDSM4(b0, b1, b2, b3,
                  sbB + SWZ(rB0 + (unsigned)(ng16 * 16 * 128) + kc * 32 + hb));
            MMA(acc[0][2 * ng16],     a0[0], a0[1], a0[2], a0[3], b0, b2);
            MMA(acc[0][2 * ng16 + 1], a0[0], a0[1], a0[2], a0[3], b1, b3);
            MMA(acc[1][2 * ng16],     a1[0], a1[1], a1[2], a1[3], b0, b2);
            MMA(acc[1][2 * ng16 + 1], a1[0], a1[1], a1[2], a1[3], b1, b3);
        }
    }

    #pragma unroll
    for (int mg = 0; mg < 2; mg++) {
        const int r0l = wr * 32 + mg * 16 + (lane >> 2);
        const int r1l = r0l + 8;
        const int r0g = bN + n0 + r0l;
        const int r1g = r0g + 8;
        const float thr0 = g_norm[r0g] - 2.0f;
        const float thr1 = g_norm[r1g] - 2.0f;
        int* cl0 = g_cidx + ((size_t)r0g << 12);
        int* cl1 = g_cidx + ((size_t)r1g << 12);
        #pragma unroll
        for (int ng = 0; ng < 8; ng++) {
            const int coll = wc * 64 + ng * 8 + 2 * (lane & 3);
            const int colg = m0 + coll;
            const float* a = acc[mg][ng];
            if (a[0] > thr0) { int p = atomicAdd(&g_cnt[r0g], 1); cl0[p] = colg; }
            if (a[1] > thr0) { int p = atomicAdd(&g_cnt[r0g], 1); cl0[p] = colg + 1; }
            if (a[2] > thr1) { int p = atomicAdd(&g_cnt[r1g], 1); cl1[p] = colg; }
            if (a[3] > thr1) { int p = atomicAdd(&g_cnt[r1g], 1); cl1[p] = colg + 1; }
            if (offdiag) {
                const float tc0 = s_nC[coll] - 2.0f;
                const float tc1 = s_nC[coll + 1] - 2.0f;
                const int c0g = bN + colg;
                const int c1g = c0g + 1;
                if (a[0] > tc0) { int p = atomicAdd(&g_cnt[c0g], 1);
                                  g_cidx[((size_t)c0g << 12) + p] = n0 + r0l; }
                if (a[1] > tc1) { int p = atomicAdd(&g_cnt[c1g], 1);
                                  g_cidx[((size_t)c1g << 12) + p] = n0 + r0l; }
                if (a[2] > tc0) { int p = atomicAdd(&g_cnt[c0g], 1);
                                  g_cidx[((size_t)c0g << 12) + p] = n0 + r1l; }
                if (a[3] > tc1) { int p = atomicAdd(&g_cnt[c1g], 1);
                                  g_cidx[((size_t)c1g << 12) + p] = n0 + r1l; }
            }
        }
    }
}

// ---------------------------------------------------------------------------
// Solve (block per row): exact fp32 dots, Michelot (tau0=-1), coalesced scatter
// ---------------------------------------------------------------------------
__global__ __launch_bounds__(256) void solve_scatter_kernel()
{
    __shared__ int   s_idx[SCAP];
    __shared__ float s_val[SCAP];
    __shared__ float s_rf[8];
    __shared__ int   s_ri[8];
    __shared__ float s_Mex;
    __shared__ int   s_pk;
    __shared__ int   s_pidx[SCAP];
    __shared__ float s_pv[SCAP];

    const int n    = blockIdx.x;
    const int b    = blockIdx.y;
    const int t    = threadIdx.x;
    const int wid  = t >> 5;
    const int lane = t & 31;
    const int bN   = b * NPIX;
    const int row  = bN + n;

    const int c = g_cnt[row];
    if (t == 0) s_pk = 0;
    int*   gl = g_cidx + ((size_t)row << 12);
    const bool small = (c <= SCAP);
    int*   idx = small ? s_idx : gl;
    float* val = small ? s_val : (g_vals + ((size_t)row << 12));
    if (small)
        for (int j = t; j < c; j += 256) s_idx[j] = gl[j];
    __syncthreads();

    {
        const float2 en = *(const float2*)&g_et[(size_t)row * CR + lane * 2];
        for (int j = wid; j < c; j += 8) {
            int mcol = idx[j];
            float2 em = *(const float2*)&g_et[(size_t)(bN + mcol) * CR + lane * 2];
            float sum = en.x * em.x + en.y * em.y;
            #pragma unroll
            for (int o = 16; o; o >>= 1) sum += __shfl_xor_sync(0xffffffffu, sum, o);
            if (lane == 0) val[j] = sum;
        }
    }
    __syncthreads();

    {
        float mm = -3.0e38f;
        for (int j = t; j < c; j += 256) mm = fmaxf(mm, val[j]);
        #pragma unroll
        for (int o = 16; o; o >>= 1) mm = fmaxf(mm, __shfl_xor_sync(0xffffffffu, mm, o));
        if (lane == 0) s_rf[wid] = mm;
        __syncthreads();
        if (t == 0) {
            float v = s_rf[0];
            #pragma unroll
            for (int w = 1; w < 8; w++) v = fmaxf(v, s_rf[w]);
            s_Mex = v;
        }
        __syncthreads();
    }
    const float Mex = s_Mex;

    float tau = -1.0f;
    int prev = -1;
    for (int it = 0; it < 32; it++) {
        float ss = 0.f; int cnt = 0;
        for (int j = t; j < c; j += 256) {
            float z = val[j] - Mex;
            if (z > tau) { ss += z; cnt++; }
        }
        #pragma unroll
        for (int o = 16; o; o >>= 1) {
            ss  += __shfl_xor_sync(0xffffffffu, ss, o);
            cnt += __shfl_xor_sync(0xffffffffu, cnt, o);
        }
        if (lane == 0) { s_rf[wid] = ss; s_ri[wid] = cnt; }
        __syncthreads();
        float tss = 0.f; int tcn = 0;
        #pragma unroll
        for (int w = 0; w < 8; w++) { tss += s_rf[w]; tcn += s_ri[w]; }
        __syncthreads();
        tau = (tss - 1.f) / (float)tcn;
        if (tcn == prev) break;
        prev = tcn;
    }

    const unsigned lt_mask = (1u << lane) - 1u;
    for (int j0 = 0; j0 < c; j0 += 256) {
        int j = j0 + t;
        float p = 0.f;
        bool pos = false;
        if (j < c) {
            p = val[j] - Mex - tau;
            pos = p > 0.f;
        }
        unsigned mk = __ballot_sync(0xffffffffu, pos);
        int base = 0;
        if (lane == 0 && mk) base = atomicAdd(&s_pk, __popc(mk));
        base = __shfl_sync(0xffffffffu, base, 0);
        if (pos) {
            int pi = base + __popc(mk & lt_mask);
            if (pi < SCAP) { s_pidx[pi] = idx[j]; s_pv[pi] = p; }
        }
    }
    __syncthreads();

    const float xv = g_xt[(size_t)row * CIN + t];
    float* ot = g_outt + (size_t)bN * CIN;
    if (s_pk <= SCAP) {
        const int kp = s_pk;
        for (int jj = 0; jj < kp; jj++)
            atomicAdd(&ot[(size_t)s_pidx[jj] * CIN + t], s_pv[jj] * xv);
    } else {
        for (int j = 0; j < c; j++) {
            float p = val[j] - Mex - tau;
            if (p > 0.f)
                atomicAdd(&ot[(size_t)idx[j] * CIN + t], p * xv);
        }
    }
}

// ---------------------------------------------------------------------------
// out[b][c][n] = x[b][c][n] + outt[b][n][c]
// ---------------------------------------------------------------------------
__global__ __launch_bounds__(256) void final_add_kernel(
    const float* __restrict__ x, float* __restrict__ out)
{
    __shared__ float s[32][33];
    const int b  = blockIdx.z;
    const int n0 = blockIdx.x * 32;
    const int c0 = blockIdx.y * 32;
    const int tx = threadIdx.x, ty = threadIdx.y;
    #pragma unroll
    for (int j = 0; j < 4; j++) {
        int n = n0 + ty + j * 8;
        s[ty + j * 8][tx] = g_outt[((size_t)(b * NPIX) + n) * CIN + c0 + tx];
    }
    __syncthreads();
    #pragma unroll
    for (int j = 0; j < 4; j++) {
        int c = c0 + ty + j * 8;
        size_t o = (size_t)(b * CIN + c) * NPIX + n0 + tx;
        out[o] = x[o] + s[tx][ty + j * 8];
    }
}

// ---------------------------------------------------------------------------
extern "C" void kernel_launch(void* const* d_in, const int* in_sizes, int n_in,
                              void* d_out, int out_size)
{
    const float* x      = (const float*)d_in[0];
    const float* conv_w = (const float*)d_in[1];
    const float* conv_b = (const float*)d_in[2];
    const float* gamma  = (const float*)d_in[3];
    const float* beta   = (const float*)d_in[4];
    const float* mean   = (const float*)d_in[5];
    const float* var    = (const float*)d_in[6];
    const float* prelu  = (const float*)d_in[7];
    float* out = (float*)d_out;

    // conv in the profiled (4th) slot
    zero_kernel<<<2048, 256>>>();

    wt_kernel<<<(CR * CIN * 9 + 255) / 256, 256>>>(conv_w);

    init_transpose_kernel<<<dim3(NPIX / 32, CIN / 32, BATCH), dim3(32, 8)>>>(x);

    conv_partial_kernel<<<dim3(HH / 2, 4, BATCH), 256>>>(x);

    conv_epilogue_kernel<<<dim3(NPIX / 32, BATCH), 256>>>(
        conv_b, gamma, beta, mean, var, prelu);

    gemm_filter_sym_kernel<<<dim3(32, 32, BATCH), 256>>>();

    solve_scatter_kernel<<<dim3(NPIX, BATCH), 256>>>();

    final_add_kernel<<<dim3(NPIX / 32, CIN / 32, BATCH), dim3(32, 8)>>>(x, out);
}